// round 14
// baseline (speedup 1.0000x reference)
#include <cuda_runtime.h>
#include <cstdint>
#include <cstddef>

#define T_LEN 1000
#define B_SZ  512
#define C_IN  22
#define H_SZ  64
#define TH    (T_LEN * H_SZ)  // 64000

typedef unsigned long long ull;

// xproj: ull index = (t*256 + rp)*256 + col (natural col order); lanes = (rowX,rowY)
__device__ ull    g_xproj[(size_t)T_LEN * 256 * 256];
// wfcT2: float2 index = (t*2 + ch)*64 + u ; value = (class 2ch, class 2ch+1)
__device__ float2 g_wfcT2[(size_t)T_LEN * 2 * 64];

__device__ __forceinline__ ull pack2f(float lo, float hi) {
    ull r;
    uint32_t a = __float_as_uint(lo), b = __float_as_uint(hi);
    asm("mov.b64 %0, {%1, %2};" : "=l"(r) : "r"(a), "r"(b));
    return r;
}
__device__ __forceinline__ ull splat2(float w) {
    ull r;
    uint32_t u = __float_as_uint(w);
    asm("mov.b64 %0, {%1, %1};" : "=l"(r) : "r"(u));
    return r;
}
__device__ __forceinline__ void ffma2(ull& d, ull a, ull b) {
    asm("fma.rn.f32x2 %0, %1, %2, %3;" : "=l"(d) : "l"(a), "l"(b), "l"(d));
}
__device__ __forceinline__ void unpack2(ull v, float& lo, float& hi) {
    uint32_t ulo, uhi;
    asm("mov.b64 {%0, %1}, %2;" : "=r"(ulo), "=r"(uhi) : "l"(v));
    lo = __uint_as_float(ulo);
    hi = __uint_as_float(uhi);
}
__device__ __forceinline__ float tanh_fast(float x) {
    float y;
    asm("tanh.approx.f32 %0, %1;" : "=f"(y) : "f"(x));
    return y;
}

// ---------------------------------------------------------------------------
// Kernel A: x_proj precompute (row-pair packed, bias included, natural cols).
// grid = (256 row-pairs, 8 t-tiles of 128), block = 256. 2 timesteps/iter.
// ---------------------------------------------------------------------------
__global__ void __launch_bounds__(256) xproj_kernel(
    const float* __restrict__ x, const float* __restrict__ W_ih,
    const float* __restrict__ b_ih, const float* __restrict__ b_hh)
{
    __shared__ __align__(16) ull xs[C_IN][128];   // [ch][tt], lanes = row pair

    const int j  = threadIdx.x;                   // gate column
    const int rp = blockIdx.x;
    const int t0 = blockIdx.y * 128;
    const int tlen = (t0 + 128 <= T_LEN) ? 128 : (T_LEN - t0);   // 128 or 104 (even)

    const float* xbase = x + (size_t)(2 * rp) * C_IN * T_LEN;
    for (int idx = j; idx < 2 * C_IN * 128; idx += 256) {
        int r   = idx / (C_IN * 128);
        int rem = idx - r * (C_IN * 128);
        int c   = rem >> 7;
        int tt  = rem & 127;
        float v = (tt < tlen) ? xbase[(size_t)r * C_IN * T_LEN + c * T_LEN + t0 + tt] : 0.f;
        ((float*)&xs[c][tt])[r] = v;
    }

    ull wih2[C_IN];
#pragma unroll
    for (int c = 0; c < C_IN; c++) wih2[c] = splat2(W_ih[j * C_IN + c]);
    const ull bias2 = splat2(b_ih[j] + b_hh[j]);
    __syncthreads();

    for (int i = 0; i < tlen; i += 2) {
        ull a0 = bias2, a1 = bias2;
#pragma unroll
        for (int c = 0; c < C_IN; c++) {
            ulonglong2 xc = *(const ulonglong2*)&xs[c][i];   // tt i, i+1 (broadcast)
            ffma2(a0, wih2[c], xc.x);
            ffma2(a1, wih2[c], xc.y);
        }
        size_t base = ((size_t)(t0 + i) * 256 + rp) * 256 + j;
        g_xproj[base]         = a0;
        g_xproj[base + 65536] = a1;   // next t: +256*256
    }
}

// ---------------------------------------------------------------------------
// Kernel B: W_fc -> class-half float2 layout  [(t*2+ch)*64+u] = (c_{2ch}, c_{2ch+1})
// ---------------------------------------------------------------------------
__global__ void wfcT_kernel(const float* __restrict__ W_fc) {
    int i = blockIdx.x * 256 + threadIdx.x;   // i = t*64+u
    if (i < TH) {
        int t = i >> 6, u = i & 63;
        g_wfcT2[(size_t)(t * 2 + 0) * 64 + u] = make_float2(W_fc[i],          W_fc[TH + i]);
        g_wfcT2[(size_t)(t * 2 + 1) * 64 + u] = make_float2(W_fc[2 * TH + i], W_fc[3 * TH + i]);
    }
}

// ---------------------------------------------------------------------------
// Kernel C: fused LSTM + FC + softmax. R6 skeleton, phase B on ALL 8 warps.
// grid = 256 CTAs (rows X=2cta, Y=2cta+1), block = 256, 2 CTAs/SM.
// Phase A: thread j = gate column j, both rows (4 FFMA2 chains + xproj add).
// Phase B: thread j = (unit u=j&63, row=(j>>6)&1, class-half ch=j>>7).
// ---------------------------------------------------------------------------
__global__ void __launch_bounds__(256, 2) lstm_fused(
    const float* __restrict__ W_hh, const float* __restrict__ b_fc,
    float* __restrict__ out)
{
    __shared__ __align__(16) ull hXp[32], hYp[32];   // h unit-pair packed
    __shared__ float g2f[2][256];                    // gates per row plane
    __shared__ float red[2 * 4 * 64];
    __shared__ float logits_sh[2][4];

    const int j   = threadIdx.x;
    const int cta = blockIdx.x;

    // ---- phase-A identity: gate column j ----
    ull whhp[32];
    {
        const float4* wp = reinterpret_cast<const float4*>(W_hh + j * H_SZ);
#pragma unroll
        for (int k = 0; k < 16; k++) {
            float4 v = wp[k];
            whhp[2*k]   = pack2f(v.x, v.y);
            whhp[2*k+1] = pack2f(v.z, v.w);
        }
    }
    const bool  is_g   = ((j >> 6) == 2);    // cols 128..191 = g-gate
    const float nl_pre = is_g ? 1.f : 0.5f;
    const float nl_sc  = is_g ? 1.f : 0.5f;
    const float nl_off = is_g ? 0.f : 0.5f;

    // ---- phase-B identity ----
    const int u   = j & 63;
    const int row = (j >> 6) & 1;
    const int ch  = j >> 7;
    float c_state = 0.f;
    float p0 = 0.f, p1 = 0.f;                        // classes 2ch, 2ch+1
    float2 wf2 = g_wfcT2[(size_t)ch * 64 + u];       // t=0

    if (j < 32)       hXp[j] = 0ull;
    else if (j < 64)  hYp[j - 32] = 0ull;

    // xproj prefetch (coalesced, natural col order)
    const ull* xq = g_xproj + (size_t)cta * 256 + j;
    ull xv = xq[0];
    __syncthreads();

    for (int t = 0; t < T_LEN; t++) {
        // ---- phase A: gate GEMV over h (both rows) ----
        ull aX0 = 0ull, aX1 = 0ull, aY0 = 0ull, aY1 = 0ull;
        const ulonglong2* hpX = reinterpret_cast<const ulonglong2*>(hXp);
        const ulonglong2* hpY = reinterpret_cast<const ulonglong2*>(hYp);
#pragma unroll
        for (int k = 0; k < 16; k++) {
            ulonglong2 hA = hpX[k];
            ulonglong2 hB = hpY[k];
            ffma2(aX0, whhp[2*k],     hA.x);
            ffma2(aY0, whhp[2*k],     hB.x);
            ffma2(aX1, whhp[2*k + 1], hA.y);
            ffma2(aY1, whhp[2*k + 1], hB.y);
        }

        // prefetch xproj(t+1) — overlaps the chains above
        const int tn = (t + 1 < T_LEN) ? t + 1 : t;
        ull xn = xq[(size_t)tn * 65536];

        // combine + nonlinearity
        float xpX, xpY, s, h2;
        unpack2(xv, xpX, xpY);
        unpack2(aX0, s, h2); float sX = s + h2;
        unpack2(aX1, s, h2); float vX = sX + (s + h2) + xpX;
        unpack2(aY0, s, h2); float sY = s + h2;
        unpack2(aY1, s, h2); float vY = sY + (s + h2) + xpY;
        g2f[0][j] = fmaf(nl_sc, tanh_fast(nl_pre * vX), nl_off);
        g2f[1][j] = fmaf(nl_sc, tanh_fast(nl_pre * vY), nl_off);
        xv = xn;
        __syncthreads();   // BAR1: gates visible

        // ---- phase B: ALL 256 threads; (u, row, ch) ----
        {
            float i_ = g2f[row][u];
            float f_ = g2f[row][ 64 + u];
            float g_ = g2f[row][128 + u];
            float o_ = g2f[row][192 + u];
            c_state = fmaf(f_, c_state, i_ * g_);
            float h = o_ * tanh_fast(c_state);

            if (ch == 0) {   // one writer per (u,row); both ch computed same h
                float* hdst = row ? (float*)hYp : (float*)hXp;
                hdst[u] = h;
            }
            p0 = fmaf(h, wf2.x, p0);
            p1 = fmaf(h, wf2.y, p1);
            wf2 = g_wfcT2[(size_t)(tn * 2 + ch) * 64 + u];   // prefetch next step
        }
        __syncthreads();   // BAR2: h(t) visible; g2f reusable
    }

    // ---- FC reduction + softmax ----
    red[(row * 4 + 2 * ch + 0) * 64 + u] = p0;
    red[(row * 4 + 2 * ch + 1) * 64 + u] = p1;
    __syncthreads();
    if (j < 8) {
        int rr = j >> 2, nn = j & 3;
        float sum = 0.f;
#pragma unroll
        for (int k = 0; k < 64; k++) sum += red[(rr * 4 + nn) * 64 + k];
        logits_sh[rr][nn] = sum + b_fc[nn];
    }
    __syncthreads();
    if (j < 2) {
        float l0 = logits_sh[j][0], l1 = logits_sh[j][1];
        float l2 = logits_sh[j][2], l3 = logits_sh[j][3];
        float m  = fmaxf(fmaxf(l0, l1), fmaxf(l2, l3));
        float q0 = __expf(l0 - m), q1 = __expf(l1 - m);
        float q2 = __expf(l2 - m), q3 = __expf(l3 - m);
        float inv = 1.f / (q0 + q1 + q2 + q3);
        float* o = out + (2 * cta + j) * 4;
        o[0] = q0 * inv; o[1] = q1 * inv; o[2] = q2 * inv; o[3] = q3 * inv;
    }
}

// ---------------------------------------------------------------------------
extern "C" void kernel_launch(void* const* d_in, const int* in_sizes, int n_in,
                              void* d_out, int out_size) {
    const float* x    = (const float*)d_in[0];
    const float* W_ih = (const float*)d_in[1];
    const float* W_hh = (const float*)d_in[2];
    const float* b_ih = (const float*)d_in[3];
    const float* b_hh = (const float*)d_in[4];
    const float* W_fc = (const float*)d_in[5];
    const float* b_fc = (const float*)d_in[6];
    float* out = (float*)d_out;

    xproj_kernel<<<dim3(256, 8), 256>>>(x, W_ih, b_ih, b_hh);
    wfcT_kernel<<<(TH + 255) / 256, 256>>>(W_fc);
    lstm_fused<<<256, 256>>>(W_hh, b_fc, out);
}